// round 17
// baseline (speedup 1.0000x reference)
#include <cuda_runtime.h>
#include <cuda_fp16.h>
#include <cstdint>
#include <math.h>

typedef unsigned int uint;
typedef unsigned long long ull;
typedef unsigned short ushort;

// ---------------------------------------------------------------------------
// Problem constants
// ---------------------------------------------------------------------------
#define BGR   16384
#define NPG   9
#define NNODE (BGR * NPG)      // 147456
#define DM    128
#define DFF   512
#define NL    4
#define EPG   16

#define NTILES (NNODE / 128)   // 1152

// smem tile geometry: 128 rows x 128 fp16, padded row stride 272 B (17x16B)
#define LDT_B   272
#define TILE_B  (128 * LDT_B)          // 34816

// layer kernel smem: P (agg activations), Q (Wg->W2c), R (W1c)
#define P_O     0
#define Q_O     (1 * TILE_B)
#define R_O     (2 * TILE_B)
#define LM_SMEM (3 * TILE_B)           // 104448

// ---------------------------------------------------------------------------
// Scratch — activations and weights: single fp16 planes.
// ---------------------------------------------------------------------------
__device__ ushort g_hh [(size_t)NNODE * DM];
__device__ float  g_inv[NNODE];
__device__ ushort g_Wgh[(size_t)NL * DM * DM];
__device__ ushort g_W1h[(size_t)NL * DFF * DM];
__device__ ushort g_W2h[(size_t)NL * DM * DFF];

// ---------------------------------------------------------------------------
// helpers
// ---------------------------------------------------------------------------
__device__ __forceinline__ uint smem_u32(const void* p) {
    uint a;
    asm("{ .reg .u64 t; cvta.to.shared.u64 t, %1; cvt.u32.u64 %0, t; }" : "=r"(a) : "l"(p));
    return a;
}
__device__ __forceinline__ void ldsm4(uint* r, uint addr) {
    asm volatile("ldmatrix.sync.aligned.m8n8.x4.shared.b16 {%0,%1,%2,%3}, [%4];"
        : "=r"(r[0]), "=r"(r[1]), "=r"(r[2]), "=r"(r[3]) : "r"(addr));
}
__device__ __forceinline__ void mma_f16(float* c, const uint* a, const uint* b) {
    asm volatile("mma.sync.aligned.m16n8k16.row.col.f32.f16.f16.f32 "
        "{%0,%1,%2,%3}, {%4,%5,%6,%7}, {%8,%9}, {%0,%1,%2,%3};"
        : "+f"(c[0]), "+f"(c[1]), "+f"(c[2]), "+f"(c[3])
        : "r"(a[0]), "r"(a[1]), "r"(a[2]), "r"(a[3]), "r"(b[0]), "r"(b[1]));
}
__device__ __forceinline__ uint pk2f16(float v0, float v1) {
    uint r;
    asm("cvt.rn.f16x2.f32 %0, %1, %2;" : "=r"(r) : "f"(v1), "f"(v0));
    return r;
}
__device__ __forceinline__ float f16f(uint bits16) {
    float f;
    asm("cvt.f32.f16 %0, %1;" : "=f"(f) : "h"((ushort)bits16));
    return f;
}

#define CP16(sm, gp) do {                                                     \
    unsigned long long _g;                                                    \
    asm("cvta.to.global.u64 %0, %1;" : "=l"(_g) : "l"(gp));                   \
    asm volatile("cp.async.cg.shared.global [%0], [%1], 16;" :: "r"(sm), "l"(_g)); \
} while (0)
#define CP_COMMIT() asm volatile("cp.async.commit_group;" ::: "memory")
#define CP_WAIT(n)  asm volatile("cp.async.wait_group %0;" :: "n"(n) : "memory")

// async load of one 128x128 fp16 plane
__device__ __forceinline__ void cpa_tile1(const ushort* __restrict__ gp,
                                          int row0, int col0, int ldg,
                                          uint sbase, int tid) {
#pragma unroll
    for (int i = 0; i < 8; i++) {
        int idx = tid + 256 * i;
        int r = idx >> 4, g = idx & 15;
        CP16(sbase + r * LDT_B + g * 16, gp + (size_t)(row0 + r) * ldg + col0 + g * 8);
    }
}

// ---------------------------------------------------------------------------
// full-N MMA: warp tile 16(M) x 128(N), single-pass fp16, depth-2 B pipeline.
// ---------------------------------------------------------------------------
__device__ __forceinline__ void ldfragB(uint bP, uint offB, int it, uint f[8]) {
    int ks = it >> 2, pp = it & 3;
    uint ob0 = offB + (uint)((2 * pp) * 16 * LDT_B) + (uint)(ks * 32);
    uint ob1 = ob0 + 16 * LDT_B;
    ldsm4(f + 0, bP + ob0);
    ldsm4(f + 4, bP + ob1);
}

__device__ __forceinline__ void mma_fullN(const uint aH[8][4],
                                          uint bP, uint offB,
                                          float acc[16][4]) {
    uint f[2][8];
    ldfragB(bP, offB, 0, f[0]);
#pragma unroll
    for (int it = 0; it < 32; it++) {
        if (it < 31) ldfragB(bP, offB, it + 1, f[(it + 1) & 1]);
        const uint* F = f[it & 1];
        int ks = it >> 2, pp = it & 3;
        mma_f16(acc[4 * pp + 0], aH[ks], &F[0]);
        mma_f16(acc[4 * pp + 1], aH[ks], &F[2]);
        mma_f16(acc[4 * pp + 2], aH[ks], &F[4]);
        mma_f16(acc[4 * pp + 3], aH[ks], &F[6]);
    }
}

// ---------------------------------------------------------------------------
// K0: degree -> inv_sqrt_deg
// ---------------------------------------------------------------------------
__global__ void deg_kernel(const int* __restrict__ dst) {
    int g = blockIdx.x * blockDim.x + threadIdx.x;
    if (g >= BGR) return;
    int base = g * NPG;
    int cnt[NPG];
#pragma unroll
    for (int j = 0; j < NPG; j++) cnt[j] = 1;
#pragma unroll
    for (int e = 0; e < EPG; e++) {
        int dl = dst[g * EPG + e] - base;
#pragma unroll
        for (int j = 0; j < NPG; j++) cnt[j] += (dl == j) ? 1 : 0;
    }
#pragma unroll
    for (int j = 0; j < NPG; j++)
        g_inv[base + j] = rsqrtf((float)cnt[j]);
}

// ---------------------------------------------------------------------------
// K1: embedding -> fp16 h plane
// ---------------------------------------------------------------------------
__global__ void embed_kernel(const float4* __restrict__ opt,
                             const float4* __restrict__ de,
                             const int* __restrict__ op_idx) {
    int idx = blockIdx.x * blockDim.x + threadIdx.x;   // NNODE*32
    int n = idx >> 5, c = idx & 31;
    float4 t = opt[op_idx[n] * 32 + c];
    float4 d = de[c];
    uint u0 = pk2f16(t.x + d.x, t.y + d.y);
    uint u1 = pk2f16(t.z + d.z, t.w + d.w);
    *reinterpret_cast<uint2*>(g_hh + (size_t)n * DM + 4 * c) = make_uint2(u0, u1);
}

// ---------------------------------------------------------------------------
// Weight prep: plane[c][r] = fp16(src[r][c])
// ---------------------------------------------------------------------------
__global__ void prep_w(const float* __restrict__ src,
                       ushort* __restrict__ dh, int R, int C) {
    int l = blockIdx.z;
    src += (size_t)l * R * C;
    dh  += (size_t)l * R * C;
    int n = blockIdx.x * blockDim.x + threadIdx.x;
    if (n >= R * C) return;
    int c = n / R, r = n % R;
    dh[n] = (ushort)(pk2f16(src[(size_t)r * C + c], 0.f) & 0xffffu);
}

// ---------------------------------------------------------------------------
// K3: fused layer: agg (warp-per-graph, in prologue) + GEMMs,
// register-resident intermediates, fp16 single-pass.
// ---------------------------------------------------------------------------
__global__ __launch_bounds__(256) void layer_mm(
    const ushort* __restrict__ Wgh,
    const ushort* __restrict__ W1h,
    const ushort* __restrict__ W2h,
    const float* __restrict__ bg, const float* __restrict__ lng,
    const float* __restrict__ lnb, const float* __restrict__ b1,
    const float* __restrict__ b2,
    const int* __restrict__ src, const int* __restrict__ dst) {

    extern __shared__ char dsm[];
    __shared__ __align__(16) float sBg[DM], sLng[DM], sLnb[DM], sB1[DFF], sB2[DM];
    __shared__ ushort hscr[8][NPG * DM];   // per-warp gather strip (18432 B)

    int tid = threadIdx.x, lane = tid & 31, wid = tid >> 5;
    int gid = lane >> 2, tig = lane & 3;
    int colb = 2 * tig;
    uint sb = smem_u32(dsm);
    int m0 = blockIdx.x * 128;

    // async weight prefetch: Wg -> Q (G1); W1_0 -> R (G2)
    cpa_tile1(Wgh, 0, 0, DM, sb + Q_O, tid);
    CP_COMMIT();
    cpa_tile1(W1h, 0, 0, DM, sb + R_O, tid);
    CP_COMMIT();

    if (tid < DM) { sBg[tid] = bg[tid]; sLng[tid] = lng[tid]; sLnb[tid] = lnb[tid]; sB2[tid] = b2[tid]; }
    for (int i = tid; i < DFF; i += 256) sB1[i] = b1[i];

    // ---- fused aggregation prologue: warp w handles graphs G0+2w, G0+2w+1
    {
        int G0 = m0 / NPG;
        int G1 = (m0 + 127) / NPG;
#pragma unroll
        for (int t = 0; t < 2; t++) {
            int g = G0 + 2 * wid + t;
            if (g <= G1) {
                int nbase = g * NPG;
                uint2 hrow[NPG];
#pragma unroll
                for (int j = 0; j < NPG; j++) {
                    hrow[j] = *reinterpret_cast<const uint2*>(
                        g_hh + (size_t)(nbase + j) * DM + lane * 4);
                    *reinterpret_cast<uint2*>(&hscr[wid][j * DM + lane * 4]) = hrow[j];
                }
                float iv9[NPG];
#pragma unroll
                for (int j = 0; j < NPG; j++) iv9[j] = g_inv[nbase + j];
                int sl[EPG], dl[EPG];
#pragma unroll
                for (int e = 0; e < EPG; e++) {
                    sl[e] = src[g * EPG + e] - nbase;
                    dl[e] = dst[g * EPG + e] - nbase;
                }
                __syncwarp();
#pragma unroll
                for (int j = 0; j < NPG; j++) {
                    int tr = nbase + j - m0;
                    if (0 <= tr && tr < 128) {
                        float iv = iv9[j];
                        float w0 = iv * iv;
                        float a0 = w0 * f16f(hrow[j].x & 0xffffu);
                        float a1 = w0 * f16f(hrow[j].x >> 16);
                        float a2 = w0 * f16f(hrow[j].y & 0xffffu);
                        float a3 = w0 * f16f(hrow[j].y >> 16);
#pragma unroll
                        for (int e = 0; e < EPG; e++) {
                            if (dl[e] == j) {       // warp-uniform
                                float w = iv9[sl[e]] * iv;
                                uint2 hv = *reinterpret_cast<const uint2*>(
                                    &hscr[wid][sl[e] * DM + lane * 4]);
                                a0 += w * f16f(hv.x & 0xffffu);
                                a1 += w * f16f(hv.x >> 16);
                                a2 += w * f16f(hv.y & 0xffffu);
                                a3 += w * f16f(hv.y >> 16);
                            }
                        }
                        uint2 o = make_uint2(pk2f16(a0, a1), pk2f16(a2, a3));
                        *reinterpret_cast<uint2*>(dsm + P_O + tr * LDT_B + lane * 8) = o;
                    }
                }
                __syncwarp();               // strip reuse between t=0 and t=1
            }
        }
    }

    uint offA = (uint)((wid * 16 + (lane & 15)) * LDT_B + ((lane >> 4) << 4));
    uint offB = (uint)(((lane & 7) + ((lane >> 4) << 3)) * LDT_B + (((lane >> 3) & 1) << 4));

    // ---- GCN: acc = agg @ Wg --------------------------------------------
    uint hAh[8][4];
    float acc[16][4];
#pragma unroll
    for (int i = 0; i < 16; i++) { acc[i][0] = acc[i][1] = acc[i][2] = acc[i][3] = 0.f; }

    CP_WAIT(1);                            // Wg resident
    __syncthreads();                       // P fully written by all warps
#pragma unroll
    for (int ks = 0; ks < 8; ks++)
        ldsm4(hAh[ks], sb + P_O + offA + ks * 32);
    mma_fullN(hAh, sb + Q_O, offB, acc);

    // ---- bias + relu + LayerNorm entirely in registers ------------------
    float s0 = 0.f, s1 = 0.f, q0 = 0.f, q1 = 0.f;
#pragma unroll
    for (int in = 0; in < 16; in++) {
        float2 bb = *reinterpret_cast<const float2*>(&sBg[in * 8 + colb]);
        float v;
        v = fmaxf(acc[in][0] + bb.x, 0.f); acc[in][0] = v; s0 += v; q0 += v * v;
        v = fmaxf(acc[in][1] + bb.y, 0.f); acc[in][1] = v; s0 += v; q0 += v * v;
        v = fmaxf(acc[in][2] + bb.x, 0.f); acc[in][2] = v; s1 += v; q1 += v * v;
        v = fmaxf(acc[in][3] + bb.y, 0.f); acc[in][3] = v; s1 += v; q1 += v * v;
    }
    s0 += __shfl_xor_sync(0xffffffffu, s0, 1); s0 += __shfl_xor_sync(0xffffffffu, s0, 2);
    s1 += __shfl_xor_sync(0xffffffffu, s1, 1); s1 += __shfl_xor_sync(0xffffffffu, s1, 2);
    q0 += __shfl_xor_sync(0xffffffffu, q0, 1); q0 += __shfl_xor_sync(0xffffffffu, q0, 2);
    q1 += __shfl_xor_sync(0xffffffffu, q1, 1); q1 += __shfl_xor_sync(0xffffffffu, q1, 2);
    float mu0 = s0 * (1.f / 128.f), mu1 = s1 * (1.f / 128.f);
    float rs0 = rsqrtf(fmaxf(q0 * (1.f / 128.f) - mu0 * mu0, 0.f) + 1e-5f);
    float rs1 = rsqrtf(fmaxf(q1 * (1.f / 128.f) - mu1 * mu1, 0.f) + 1e-5f);

#pragma unroll
    for (int ks = 0; ks < 8; ks++) {
        int in0 = 2 * ks, in1 = 2 * ks + 1;
        float2 g0 = *reinterpret_cast<const float2*>(&sLng[in0 * 8 + colb]);
        float2 c0 = *reinterpret_cast<const float2*>(&sLnb[in0 * 8 + colb]);
        float2 g1 = *reinterpret_cast<const float2*>(&sLng[in1 * 8 + colb]);
        float2 c1 = *reinterpret_cast<const float2*>(&sLnb[in1 * 8 + colb]);
        hAh[ks][0] = pk2f16((acc[in0][0] - mu0) * rs0 * g0.x + c0.x,
                            (acc[in0][1] - mu0) * rs0 * g0.y + c0.y);
        hAh[ks][1] = pk2f16((acc[in0][2] - mu1) * rs1 * g0.x + c0.x,
                            (acc[in0][3] - mu1) * rs1 * g0.y + c0.y);
        hAh[ks][2] = pk2f16((acc[in1][0] - mu0) * rs0 * g1.x + c1.x,
                            (acc[in1][1] - mu0) * rs0 * g1.y + c1.y);
        hAh[ks][3] = pk2f16((acc[in1][2] - mu1) * rs1 * g1.x + c1.x,
                            (acc[in1][3] - mu1) * rs1 * g1.y + c1.y);
    }

    // ---- FFN loop: mid stays in registers -------------------------------
    float acc2[16][4];
#pragma unroll
    for (int i = 0; i < 16; i++) { acc2[i][0] = acc2[i][1] = acc2[i][2] = acc2[i][3] = 0.f; }

    for (int c = 0; c < 4; c++) {
        __syncthreads();                           // Q released
        cpa_tile1(W2h, 0, c * 128, DFF, sb + Q_O, tid);
        CP_COMMIT();
        CP_WAIT(1);                                // W1c resident in R
        __syncthreads();

        float acc1[16][4];
#pragma unroll
        for (int i = 0; i < 16; i++) { acc1[i][0] = acc1[i][1] = acc1[i][2] = acc1[i][3] = 0.f; }
        mma_fullN(hAh, sb + R_O, offB, acc1);

        // bias + relu -> mid A-fragments (registers only)
        uint mAh[8][4];
#pragma unroll
        for (int ks = 0; ks < 8; ks++) {
            int in0 = 2 * ks, in1 = 2 * ks + 1;
            float2 b0 = *reinterpret_cast<const float2*>(&sB1[c * 128 + in0 * 8 + colb]);
            float2 b1v = *reinterpret_cast<const float2*>(&sB1[c * 128 + in1 * 8 + colb]);
            mAh[ks][0] = pk2f16(fmaxf(acc1[in0][0] + b0.x, 0.f),
                                fmaxf(acc1[in0][1] + b0.y, 0.f));
            mAh[ks][1] = pk2f16(fmaxf(acc1[in0][2] + b0.x, 0.f),
                                fmaxf(acc1[in0][3] + b0.y, 0.f));
            mAh[ks][2] = pk2f16(fmaxf(acc1[in1][0] + b1v.x, 0.f),
                                fmaxf(acc1[in1][1] + b1v.y, 0.f));
            mAh[ks][3] = pk2f16(fmaxf(acc1[in1][2] + b1v.x, 0.f),
                                fmaxf(acc1[in1][3] + b1v.y, 0.f));
        }

        CP_WAIT(0);                                // W2c resident in Q
        __syncthreads();                           // all warps done with R
        if (c < 3) {
            cpa_tile1(W1h, (c + 1) * 128, 0, DM, sb + R_O, tid);
            CP_COMMIT();
        }
        mma_fullN(mAh, sb + Q_O, offB, acc2);
    }

    // ---- epilogue: h_out = hLN + ffn + b2, straight from registers ------
    int row0 = m0 + wid * 16 + gid, row1 = row0 + 8;
#pragma unroll
    for (int in = 0; in < 16; in++) {
        int col = in * 8 + colb;
        float2 b2v = *reinterpret_cast<const float2*>(&sB2[col]);
        int ks = in >> 1, jb = (in & 1) * 2;
        uint r0 = hAh[ks][jb], r1 = hAh[ks][jb + 1];
        float v0 = acc2[in][0] + b2v.x + f16f(r0 & 0xffffu);
        float v1 = acc2[in][1] + b2v.y + f16f(r0 >> 16);
        *reinterpret_cast<uint*>(g_hh + (size_t)row0 * DM + col) = pk2f16(v0, v1);
        v0 = acc2[in][2] + b2v.x + f16f(r1 & 0xffffu);
        v1 = acc2[in][3] + b2v.y + f16f(r1 >> 16);
        *reinterpret_cast<uint*>(g_hh + (size_t)row1 * DM + col) = pk2f16(v0, v1);
    }
}

// ---------------------------------------------------------------------------
// K6: readout
// ---------------------------------------------------------------------------
__global__ __launch_bounds__(128) void readout_kernel(const float4* __restrict__ fcw,
                                                      const float* __restrict__ fcb,
                                                      float* __restrict__ out) {
    int w = threadIdx.x >> 5, lane = threadIdx.x & 31;
    int g = blockIdx.x * 4 + w;
    size_t base = (size_t)g * NPG * DM + 4 * lane;
    float4 s = make_float4(0.f, 0.f, 0.f, 0.f);
#pragma unroll
    for (int j = 0; j < NPG; j++) {
        ushort4 hv = *reinterpret_cast<const ushort4*>(g_hh + base + j * DM);
        s.x += f16f(hv.x); s.y += f16f(hv.y); s.z += f16f(hv.z); s.w += f16f(hv.w);
    }
    float4 wv = fcw[lane];
    float p = s.x * wv.x + s.y * wv.y + s.z * wv.z + s.w * wv.w;
#pragma unroll
    for (int o = 16; o; o >>= 1) p += __shfl_xor_sync(0xffffffffu, p, o);
    if (lane == 0)
        out[g] = 1.f / (1.f + expf(-(p * (1.f / 9.f) + fcb[0])));
}

// ---------------------------------------------------------------------------
// Launcher
// ---------------------------------------------------------------------------
extern "C" void kernel_launch(void* const* d_in, const int* in_sizes, int n_in,
                              void* d_out, int out_size) {
    const float* op_table   = (const float*)d_in[0];
    const float* device_emb = (const float*)d_in[1];
    const float* Wg         = (const float*)d_in[2];
    const float* bg         = (const float*)d_in[3];
    const float* ln_g       = (const float*)d_in[4];
    const float* ln_b       = (const float*)d_in[5];
    const float* W1         = (const float*)d_in[6];
    const float* b1         = (const float*)d_in[7];
    const float* W2         = (const float*)d_in[8];
    const float* b2         = (const float*)d_in[9];
    const float* fc_w       = (const float*)d_in[10];
    const float* fc_b       = (const float*)d_in[11];
    const int*   op_idx     = (const int*)d_in[12];
    const int*   src        = (const int*)d_in[13];
    const int*   dst        = (const int*)d_in[14];
    float* out = (float*)d_out;

    cudaFuncSetAttribute(layer_mm, cudaFuncAttributeMaxDynamicSharedMemorySize, LM_SMEM);

    ushort *wgh, *w1h, *w2h;
    cudaGetSymbolAddress((void**)&wgh, g_Wgh);
    cudaGetSymbolAddress((void**)&w1h, g_W1h);
    cudaGetSymbolAddress((void**)&w2h, g_W2h);

    prep_w<<<dim3((DM * DM + 255) / 256, 1, NL), 256>>>(Wg, wgh, DM, DM);
    prep_w<<<dim3((DM * DFF + 255) / 256, 1, NL), 256>>>(W1, w1h, DM, DFF);
    prep_w<<<dim3((DM * DFF + 255) / 256, 1, NL), 256>>>(W2, w2h, DFF, DM);

    deg_kernel<<<BGR / 256, 256>>>(dst);
    embed_kernel<<<(NNODE * 32) / 256, 256>>>(
        (const float4*)op_table, (const float4*)device_emb, op_idx);

    for (int l = 0; l < NL; l++) {
        size_t o1 = (size_t)l * DM * DM, o2 = (size_t)l * DFF * DM, o3 = (size_t)l * DM * DFF;
        layer_mm<<<NTILES, 256, LM_SMEM>>>(
            wgh + o1, w1h + o2, w2h + o3,
            bg + l * DM, ln_g + l * DM, ln_b + l * DM, b1 + l * DFF, b2 + l * DM,
            src, dst);
    }

    readout_kernel<<<BGR / 4, 128>>>((const float4*)fc_w, fc_b, out);
}